// round 17
// baseline (speedup 1.0000x reference)
#include <cuda_runtime.h>
#include <cuda_fp16.h>
#include <cstdint>
#include <math.h>

#define NB 128   // batch
#define NS 100   // seq len
#define NM 50    // memory slots
#define ND 128   // dim
#define T  384   // threads: 256 compute + 128 mem
#define AS 52    // padded attn row stride (floats)
#define KS 132   // padded key row stride (floats)

// Fused matrix M = W2@[er|ad] and bias = b2@[er|ad] + [er_b|ad_b]
__device__ __half g_M[ND * 2 * ND];
__device__ float  g_bias[2 * ND];

#define BAR256()         asm volatile("bar.sync 1, 256;" ::: "memory")

__device__ __forceinline__ float tanh_fast(float x) {
    float y;
    asm("tanh.approx.f32 %0, %1;" : "=f"(y) : "f"(x));
    return y;
}
__device__ __forceinline__ float sigmoid_fast(float x) {
    return fmaf(0.5f, tanh_fast(0.5f * x), 0.5f);
}
__device__ __forceinline__ uint2 f4_to_h4(float4 w) {
    const __half2 h01 = __floats2half2_rn(w.x, w.y);
    const __half2 h23 = __floats2half2_rn(w.z, w.w);
    uint2 o;
    o.x = *(const unsigned*)&h01;
    o.y = *(const unsigned*)&h23;
    return o;
}

// ---------------------------------------------------------------------------
// K0: combine W2 with er/ad (unchanged).
// ---------------------------------------------------------------------------
__global__ __launch_bounds__(256, 1)
void combine_kernel(const float* __restrict__ vu_w2,
                    const float* __restrict__ vu_b2,
                    const float* __restrict__ er_w,
                    const float* __restrict__ er_b,
                    const float* __restrict__ ad_w,
                    const float* __restrict__ ad_b) {
    __shared__ float w2row[ND];
    const int k = blockIdx.x;
    const int j = threadIdx.x;
    for (int i = j; i < ND; i += 256) w2row[i] = vu_w2[k * ND + i];
    __syncthreads();
    const float* E = (j < ND) ? er_w : ad_w;
    const int jj = j & (ND - 1);
    float acc = 0.f;
#pragma unroll 8
    for (int i = 0; i < ND; i++) acc = fmaf(w2row[i], E[i * ND + jj], acc);
    g_M[k * 2 * ND + j] = __float2half_rn(acc);
    if (k == 0) {
        float bacc = (j < ND) ? er_b[jj] : ad_b[jj];
        for (int i = 0; i < ND; i++) bacc = fmaf(vu_b2[i], E[i * ND + jj], bacc);
        g_bias[j] = bacc;
    }
}

// ---------------------------------------------------------------------------
// Fused kernel: scalar prologue (R13-style attn + q1), then the
// warp-specialized recurrence (R12 structure).
// ---------------------------------------------------------------------------
// Persistent smem (floats):
#define SM_ATTN 0                         // 100*52 = 5200
#define SM_Q1   5200                      // 100*128 = 12800 -> 18000
// Loop-phase regions (initialized after prologue):
#define SM_W1H  18000                     // 128*128 fp16 = 8192 floats
#define SM_PA   26192                     // 1024
#define SM_PC   27216                     // 2 x 1024
#define SM_READ 29264                     // 128 (tail)
#define SM_H    29392                     // 128 (tail)
#define SM_UP   29520                     // 128 (tail)
#define SM_BE   29648                     // 128
#define SM_BA   29776                     // 128
#define SM_R0   29904                     // 2 x 256
#define SM_G    30416                     // 2 x 256
#define SM_C    30928                     // 8
#define SM_V    30936                     // 6400 -> 37336
// Prologue temps (alias loop regions; dead after prologue). Disjoint from
// each other and from sAttn/sQ1:
#define TP_KEY  18000                     // 50*132 fp32 = 6600 -> 24600
#define TP_W1BH 24600                     // 128*128 fp16 = 8192 float slots -> 32792
#define TP_QE   32792                     // 100*128 fp32 = 12800 -> 45592
#define TP_IDS  45592                     // 128 ints -> 45720
#define SM_TOTF 45720
#define SMEM_BYTES (SM_TOTF * 4)

__global__ __launch_bounds__(T, 1)
void fused_kernel(const int* __restrict__ qseq,
                  const float* __restrict__ emb,
                  const float* __restrict__ keym,
                  const float* __restrict__ vu_w1,
                  const float* __restrict__ vu_b1,
                  const float* __restrict__ out_w1,
                  const float* __restrict__ out_b1,
                  const float* __restrict__ out_w2,
                  const float* __restrict__ out_b2,
                  float* __restrict__ out) {
    extern __shared__ float sm[];
    float*  sAttn = sm + SM_ATTN;
    float*  sQ1   = sm + SM_Q1;
    __half* sW1h  = (__half*)(sm + SM_W1H);
    float*  sPA   = sm + SM_PA;
    float*  sPC   = sm + SM_PC;
    float*  sRead = sm + SM_READ;
    float*  sH    = sm + SM_H;
    float*  sUp   = sm + SM_UP;
    float*  sV    = sm + SM_V;
    float*  tKey  = sm + TP_KEY;
    __half* tW1bH = (__half*)(sm + TP_W1BH);
    float*  tQe   = sm + TP_QE;
    int*    tIds  = (int*)(sm + TP_IDS);

    const int b = blockIdx.x;
    const int t = threadIdx.x;
    const int w = t >> 5;
    const int lid = t & 31;

    // ======================= PROLOGUE: attn + q1 (scalar) ==================
    if (t < NS) tIds[t] = qseq[b * NS + t];

    // key -> fp32 padded stride KS
    for (int i = t; i < NM * 32; i += T) {
        const int m = i >> 5, c4 = i & 31;
        *(float4*)(tKey + m * KS + c4 * 4) = ((const float4*)keym)[i];
    }
    // w1b (rows 128..255 of vu_w1) -> fp16
    {
        const float4* src = (const float4*)(vu_w1 + ND * ND);
        for (int i = t; i < ND * 32; i += T)
            ((uint2*)tW1bH)[i] = f4_to_h4(src[i]);
    }
    __syncthreads();   // ids visible before gather

    // qe gather -> fp32
    for (int i = t; i < NS * 32; i += T) {
        const int row = i >> 5, c4 = i & 31;
        *(float4*)(tQe + row * ND + c4 * 4) =
            ((const float4*)(emb + (size_t)tIds[row] * ND))[c4];
    }
    __syncthreads();

    // ---- logits + softmax: warp per 4 rows, lane = m; 25 quads / 12 warps
    {
        const int mB = (lid < NM - 32) ? lid + 32 : lid;
        const bool hasB = (lid < NM - 32);
        const float* kA = tKey + lid * KS;
        const float* kB = tKey + mB * KS;
        for (int rq = w; rq < 25; rq += 12) {
            float acc0[4] = {0, 0, 0, 0}, acc1[4] = {0, 0, 0, 0};
#pragma unroll 8
            for (int k4 = 0; k4 < 32; k4++) {
                const float4 a = *(const float4*)(kA + k4 * 4);
                const float4 bb = *(const float4*)(kB + k4 * 4);
#pragma unroll
                for (int r = 0; r < 4; r++) {
                    const float4 q = *(const float4*)(tQe + (rq * 4 + r) * ND + k4 * 4);
                    acc0[r] = fmaf(q.x, a.x, fmaf(q.y, a.y, fmaf(q.z, a.z, fmaf(q.w, a.w, acc0[r]))));
                    acc1[r] = fmaf(q.x, bb.x, fmaf(q.y, bb.y, fmaf(q.z, bb.z, fmaf(q.w, bb.w, acc1[r]))));
                }
            }
#pragma unroll
            for (int r = 0; r < 4; r++) {
                float v0 = acc0[r];
                float v1 = hasB ? acc1[r] : -1e30f;
                float mx = fmaxf(v0, v1);
#pragma unroll
                for (int o = 16; o; o >>= 1) mx = fmaxf(mx, __shfl_xor_sync(0xffffffffu, mx, o));
                float e0 = __expf(v0 - mx);
                float e1 = hasB ? __expf(v1 - mx) : 0.f;
                float sum = e0 + e1;
#pragma unroll
                for (int o = 16; o; o >>= 1) sum += __shfl_xor_sync(0xffffffffu, sum, o);
                const float inv = 1.f / sum;
                float* dst = sAttn + (rq * 4 + r) * AS;
                dst[lid] = e0 * inv;
                if (hasB) dst[lid + 32] = e1 * inv;
            }
        }
    }

    // ---- q1 = qe @ w1b (no bias; fp16 weights, fp32 math) ----
    {
        const int cg = t & 31;
        const int rg = t >> 5;   // 0..11
        for (int rq = rg; rq < 25; rq += 12) {
            float4 acc[4] = {{0,0,0,0},{0,0,0,0},{0,0,0,0},{0,0,0,0}};
#pragma unroll 4
            for (int k4 = 0; k4 < 32; k4++) {
                const uint2 raw0 = *(const uint2*)(tW1bH + (k4 * 4 + 0) * ND + cg * 4);
                const uint2 raw1 = *(const uint2*)(tW1bH + (k4 * 4 + 1) * ND + cg * 4);
                const uint2 raw2 = *(const uint2*)(tW1bH + (k4 * 4 + 2) * ND + cg * 4);
                const uint2 raw3 = *(const uint2*)(tW1bH + (k4 * 4 + 3) * ND + cg * 4);
                const float2 w0a = __half22float2(*(const __half2*)&raw0.x);
                const float2 w0b = __half22float2(*(const __half2*)&raw0.y);
                const float2 w1a = __half22float2(*(const __half2*)&raw1.x);
                const float2 w1b_ = __half22float2(*(const __half2*)&raw1.y);
                const float2 w2a = __half22float2(*(const __half2*)&raw2.x);
                const float2 w2b = __half22float2(*(const __half2*)&raw2.y);
                const float2 w3a = __half22float2(*(const __half2*)&raw3.x);
                const float2 w3b = __half22float2(*(const __half2*)&raw3.y);
#pragma unroll
                for (int r = 0; r < 4; r++) {
                    const float4 q = *(const float4*)(tQe + (rq * 4 + r) * ND + k4 * 4);
                    acc[r].x = fmaf(q.x, w0a.x, fmaf(q.y, w1a.x, fmaf(q.z, w2a.x, fmaf(q.w, w3a.x, acc[r].x))));
                    acc[r].y = fmaf(q.x, w0a.y, fmaf(q.y, w1a.y, fmaf(q.z, w2a.y, fmaf(q.w, w3a.y, acc[r].y))));
                    acc[r].z = fmaf(q.x, w0b.x, fmaf(q.y, w1b_.x, fmaf(q.z, w2b.x, fmaf(q.w, w3b.x, acc[r].z))));
                    acc[r].w = fmaf(q.x, w0b.y, fmaf(q.y, w1b_.y, fmaf(q.z, w2b.y, fmaf(q.w, w3b.y, acc[r].w))));
                }
            }
#pragma unroll
            for (int r = 0; r < 4; r++)
                *(float4*)(sQ1 + (rq * 4 + r) * ND + cg * 4) = acc[r];
        }
    }
    __syncthreads();   // prologue reads done; temps may be overwritten

    // ======================= LOOP-REGION INIT =======================
    for (int i = t; i < ND * ND; i += T) sW1h[i] = __float2half_rn(vu_w1[i]);
    for (int i = t; i < 2 * 1024; i += T) sPC[i] = 0.f;
    for (int i = t; i < 1032; i += T) sm[SM_R0 + i] = 0.f;
    for (int i = t; i < NM * ND; i += T) sV[i] = 0.f;
    if (t < ND) {
        sm[SM_BE + t] = g_bias[t];
        sm[SM_BA + t] = g_bias[ND + t];
    }

    // compute-role registers: fused matrix M as packed half2
    const int jq = t & 63;
    const int ks = (t >> 6) & 3;
    __half2 mh01[32], mh23[32];
    if (t < 256) {
#pragma unroll
        for (int kk = 0; kk < 32; kk++) {
            const uint2 raw = *(const uint2*)(g_M + (ks * 32 + kk) * 2 * ND + jq * 4);
            mh01[kk] = *(const __half2*)&raw.x;
            mh23[kk] = *(const __half2*)&raw.y;
        }
    }
    const int u2 = t - 256;
    const int hh = u2 >> 6;
    const int c2 = (u2 & 63) * 2;

    const int j4 = (t & 31) * 4;
    const int kg = (t >> 5) & 7;
    const int kownA = kg * 16 + (lid & 15);
    const int kownC = ks * 32 + lid;
    const float b1reg = (t < 256) ? vu_b1[kownC] : 0.f;

    __syncthreads();

    // ======================= RECURRENCE =======================
    for (int s = 0; s < NS; s++) {
        const int par  = s & 1;
        const int parm = (s + 1) & 1;

        if (t < 256) {
            const float q1f = sQ1[s * ND + kownC] + b1reg;
            const float* pc = sPC + parm * 1024;

            // A prologue: reconstruct e/a at kownA, then read value
            float rd;
            {
                float pe = sm[SM_BE + kownA];
                float pa = sm[SM_BA + kownA];
#pragma unroll
                for (int g = 0; g < 4; g++) {
                    pe += pc[g * 256 + kownA];
                    pa += pc[g * 256 + 128 + kownA];
                }
                const float e = sigmoid_fast(pe);
                const float a = tanh_fast(pa);
                const float r0 = sm[SM_R0 + par * 256 + kownA]
                               + sm[SM_R0 + par * 256 + 128 + kownA];
                const float gg = sm[SM_G + par * 256 + kownA]
                               + sm[SM_G + par * 256 + 128 + kownA];
                const float cc = sm[SM_C + par * 2] + sm[SM_C + par * 2 + 1];
                rd = fmaf(cc, a, fmaf(-e, gg, r0));
            }
            // A GEMV (fp16)
            {
                const __half2 rh2 = __float2half2_rn(rd);
                const unsigned ru = *(const unsigned*)&rh2;
                __half2 acc01 = __floats2half2_rn(0.f, 0.f);
                __half2 acc23 = acc01;
                const __half* wrow = sW1h + (kg * 16) * ND + j4;
#pragma unroll
                for (int i = 0; i < 16; i++) {
                    const unsigned xs = __shfl_sync(0xffffffffu, ru, i);
                    const __half2 xh = *(const __half2*)&xs;
                    const uint2 raw = *(const uint2*)(wrow + i * ND);
                    acc01 = __hfma2(xh, *(const __half2*)&raw.x, acc01);
                    acc23 = __hfma2(xh, *(const __half2*)&raw.y, acc23);
                }
                const float2 f01 = __half22float2(acc01);
                const float2 f23 = __half22float2(acc23);
                float4 o = {f01.x, f01.y, f23.x, f23.y};
                *(float4*)(sPA + kg * ND + j4) = o;
            }
            BAR256();

            // M prologue: h[kownC] = tanh(q1 + b1 + sum partials)
            float hv;
            {
                float v = q1f;
#pragma unroll
                for (int g = 0; g < 8; g++) v += sPA[g * ND + kownC];
                hv = tanh_fast(v);
            }
            // M GEMV (fp16): 256 pre-act outputs
            {
                const __half2 hh2 = __float2half2_rn(hv);
                const unsigned hu = *(const unsigned*)&hh2;
                __half2 acc01 = __floats2half2_rn(0.f, 0.f);
                __half2 acc23 = acc01;
#pragma unroll
                for (int i = 0; i < 32; i++) {
                    const unsigned xs = __shfl_sync(0xffffffffu, hu, i);
                    const __half2 xh = *(const __half2*)&xs;
                    acc01 = __hfma2(xh, mh01[i], acc01);
                    acc23 = __hfma2(xh, mh23[i], acc23);
                }
                const float2 p01 = __half22float2(acc01);
                const float2 p23 = __half22float2(acc23);
                float4 o = {p01.x, p01.y, p23.x, p23.y};
                *(float4*)(sPC + par * 1024 + ks * 256 + jq * 4) = o;
            }
        } else {
            // mem warps: 2 columns x half m-range
            const int moff = hh ? 24 : 0;
            const float* wub = sAttn + (s ? (s - 1) * AS : 0) + moff;
            const float* wsb = sAttn + s * AS + moff;
            const float* wrb = sAttn + ((s + 1 < NS) ? (s + 1) : (NS - 1)) * AS + moff;
            float2 ev, av;
            if (s == 0) {
                ev.x = ev.y = av.x = av.y = 0.f;
            } else {
                const float* pc = sPC + parm * 1024;
                float2 pe = *(const float2*)(sm + SM_BE + c2);
                float2 pa = *(const float2*)(sm + SM_BA + c2);
#pragma unroll
                for (int g = 0; g < 4; g++) {
                    const float2 q = *(const float2*)(pc + g * 256 + c2);
                    const float2 r = *(const float2*)(pc + g * 256 + 128 + c2);
                    pe.x += q.x; pe.y += q.y;
                    pa.x += r.x; pa.y += r.y;
                }
                ev.x = sigmoid_fast(pe.x); ev.y = sigmoid_fast(pe.y);
                av.x = tanh_fast(pa.x);    av.y = tanh_fast(pa.y);
            }
            const float nex = -ev.x, ney = -ev.y;
            float2 r0v = {0.f, 0.f}, gv = {0.f, 0.f};
            float cacc = 0.f;

#define MEM2(wum, wsm, wrm, m) { \
    float2 v = *(float2*)(sV + (m) * ND + c2); \
    v.x = fmaf(wum, fmaf(nex, v.x, av.x), v.x); \
    v.y = fmaf(wum, fmaf(ney, v.y, av.y), v.y); \
    *(float2*)(sV + (m) * ND + c2) = v; \
    const float px = (wrm) * v.x, py = (wrm) * v.y; \
    r0v.x += px; r0v.y += py; \
    gv.x = fmaf(wsm, px, gv.x); gv.y = fmaf(wsm, py, gv.y); \
    cacc = fmaf(wrm, wsm, cacc); }

#pragma unroll
            for (int q = 0; q < 6; q++) {
                const float4 wu4 = *(const float4*)(wub + q * 4);
                const float4 ws4 = *(const float4*)(wsb + q * 4);
                const float4 wr4 = *(const float4*)(wrb + q * 4);
                MEM2(wu4.x, ws4.x, wr4.x, moff + q * 4 + 0)
                MEM2(wu4.y, ws4.y, wr4.y, moff + q * 4 + 1)
                MEM2(wu4.z, ws4.z, wr4.z, moff + q * 4 + 2)
                MEM2(wu4.w, ws4.w, wr4.w, moff + q * 4 + 3)
            }
            if (hh) {
                const float2 wu2 = *(const float2*)(wub + 24);
                const float2 ws2 = *(const float2*)(wsb + 24);
                const float2 wr2 = *(const float2*)(wrb + 24);
                MEM2(wu2.x, ws2.x, wr2.x, 48)
                MEM2(wu2.y, ws2.y, wr2.y, 49)
            }
#undef MEM2
            *(float2*)(sm + SM_R0 + parm * 256 + hh * 128 + c2) = r0v;
            *(float2*)(sm + SM_G  + parm * 256 + hh * 128 + c2) = gv;
            if ((u2 & 63) == 0) sm[SM_C + parm * 2 + hh] = cacc;
        }
        __syncthreads();
    }

    // ---- tail: read_out = w_99 . v_100 via the same identity ----
    if (t < ND) {
        const float* pc = sPC + 1024;       // parity of s=99
        float pe = sm[SM_BE + t];
        float pa = sm[SM_BA + t];
#pragma unroll
        for (int g = 0; g < 4; g++) {
            pe += pc[g * 256 + t];
            pa += pc[g * 256 + 128 + t];
        }
        const float e = sigmoid_fast(pe);
        const float a = tanh_fast(pa);
        const float r0 = sm[SM_R0 + t] + sm[SM_R0 + 128 + t];   // parity 0
        const float gg = sm[SM_G + t] + sm[SM_G + 128 + t];
        const float cc = sm[SM_C] + sm[SM_C + 1];
        sRead[t] = fmaf(cc, a, fmaf(-e, gg, r0));
        const int qi = qseq[b * NS + (NS - 1)];
        sUp[t] = emb[qi * ND + t];   // qe_last
    }
    __syncthreads();

    // ---- output head ----
    if (t < 256) {
        const float* pin = (kg < 4) ? sRead : (sUp - ND);
        float4 acc = {0.f, 0.f, 0.f, 0.f};
#pragma unroll
        for (int i = 0; i < 32; i++) {
            const int k = kg * 32 + i;
            const float x = pin[k];
            const float4 wv = *(const float4*)(out_w1 + k * ND + j4);
            acc.x = fmaf(x, wv.x, acc.x);
            acc.y = fmaf(x, wv.y, acc.y);
            acc.z = fmaf(x, wv.z, acc.z);
            acc.w = fmaf(x, wv.w, acc.w);
        }
        *(float4*)(sPA + kg * ND + j4) = acc;
    }
    __syncthreads();
    if (t < ND) {
        float v = out_b1[t];
#pragma unroll
        for (int g = 0; g < 8; g++) v += sPA[g * ND + t];
        sH[t] = fmaxf(v, 0.f) * out_w2[t];
    }
    __syncthreads();
    if (t < 32) {
        float v = sH[t] + sH[t + 32] + sH[t + 64] + sH[t + 96];
#pragma unroll
        for (int o = 16; o; o >>= 1) v += __shfl_xor_sync(0xffffffffu, v, o);
        if (t == 0) out[b] = 1.f / (1.f + __expf(-(v + out_b2[0])));
    }
}

// ---------------------------------------------------------------------------
extern "C" void kernel_launch(void* const* d_in, const int* in_sizes, int n_in,
                              void* d_out, int out_size) {
    const int*   qseq   = (const int*)  d_in[0];
    // d_in[1] = answer_seq (unused by reference)
    const float* emb    = (const float*)d_in[2];
    const float* keym   = (const float*)d_in[3];
    const float* vu_w1  = (const float*)d_in[4];
    const float* vu_b1  = (const float*)d_in[5];
    const float* vu_w2  = (const float*)d_in[6];
    const float* vu_b2  = (const float*)d_in[7];
    const float* er_w   = (const float*)d_in[8];
    const float* er_b   = (const float*)d_in[9];
    const float* ad_w   = (const float*)d_in[10];
    const float* ad_b   = (const float*)d_in[11];
    const float* out_w1 = (const float*)d_in[12];
    const float* out_b1 = (const float*)d_in[13];
    const float* out_w2 = (const float*)d_in[14];
    const float* out_b2 = (const float*)d_in[15];
    float* out = (float*)d_out;

    cudaFuncSetAttribute(fused_kernel,
                         cudaFuncAttributeMaxDynamicSharedMemorySize, SMEM_BYTES);

    combine_kernel<<<ND, 256>>>(vu_w2, vu_b2, er_w, er_b, ad_w, ad_b);
    fused_kernel<<<NB, T, SMEM_BYTES>>>(qseq, emb, keym, vu_w1, vu_b1,
                                        out_w1, out_b1, out_w2, out_b2, out);
}